// round 15
// baseline (speedup 1.0000x reference)
#include <cuda_runtime.h>

// YOLO-style detection loss — R14 + L1-carveout + aligned-f2 flag loads.
// preds:  (n, 1470) f32  [pcls 980 | pconf 98 | pbox 392]
// labels: (n, 1225) f32  per cell (25 floats): [flag | 20 cls | 4 box]

#define L_CELLS 49
#define ROW_P 1470
#define ROW_L 1225
#define NOOBJ_W 0.5f
#define OBJ_W 0.5f
#define CLS_W 0.5f
#define COORD_W 2.5f

#define THREADS 256
#define CPT 4
#define CPB (THREADS * CPT)
#define NWARPS (THREADS / 32)
#define MAX_BLOCKS 8192

__device__ double   g_partials[MAX_BLOCKS];
__device__ unsigned g_counter = 0;    // self-wrapping; replay-safe

__device__ __forceinline__ float obj_cell_loss(
    const float* __restrict__ preds,
    const float* __restrict__ labels,
    int cell)
{
    int i = cell / L_CELLS;
    int l = cell - i * L_CELLS;
    const float* p = preds + (size_t)i * ROW_P;

    // ===== label window: win[k] = labels[a+k], a = lb & ~1, off = lb & 1 ====
    // record element j == win[j + off]; win[2m]=w[m].x, win[2m+1]=w[m].y
    unsigned lb  = (unsigned)i * ROW_L + 25u * l;
    unsigned a   = lb & ~1u;
    bool     off = (lb & 1u) != 0u;
    const float2* w = reinterpret_cast<const float2*>(labels + a);

    // ===== pcls window: pv[c] = preds[g4 + c + off2] ========================
    // g = i*1470 + 20l, g mod 4 in {0,2}; window g4..g4+23 stays in-row.
    unsigned g    = (unsigned)i * ROW_P + 20u * l;
    unsigned g4   = g & ~3u;
    bool     off2 = (g & 3u) != 0u;     // 0 or 2
    const float4* q = reinterpret_cast<const float4*>(preds + g4);

    // ---- issue scattered single-use loads up front (evict-first) ----
    float2 pc = __ldcs(reinterpret_cast<const float2*>(p + 980 + l * 2));
    const float* pb = p + 1078 + l * 8;
    float2 b01 = __ldcs(reinterpret_cast<const float2*>(pb + 0));
    float2 b23 = __ldcs(reinterpret_cast<const float2*>(pb + 2));
    float2 b45 = __ldcs(reinterpret_cast<const float2*>(pb + 4));
    float2 b67 = __ldcs(reinterpret_cast<const float2*>(pb + 6));

    // ===== class loss: rolling label window vs f4 pcls window ==============
    float cls = 0.0f;
    {
        float2 wc = __ldg(w + 0);            // w[c/2] for c=0
        #pragma unroll
        for (int c = 0; c < 20; c += 2) {
            float2 wn = __ldg(w + (c / 2 + 1));
            float la1 = off ? wn.x : wc.y;
            float la2 = off ? wn.y : wn.x;

            float pv1, pv2;
            if ((c & 3) == 0) {
                float4 v = __ldcs(q + c / 4);
                pv1 = off2 ? v.z : v.x;
                pv2 = off2 ? v.w : v.y;
            } else {  // c % 4 == 2
                float4 vlo = __ldcs(q + c / 4);
                float4 vhi = __ldcs(q + (c / 4 + 1));
                pv1 = off2 ? vhi.x : vlo.z;
                pv2 = off2 ? vhi.y : vlo.w;
            }
            float d0 = la1 - pv1;
            float d1 = la2 - pv2;
            cls += d0 * d0 + d1 * d1;
            wc = wn;
        }
    }
    cls *= CLS_W;

    // ===== target box: la(21..24) ===========================================
    float2 w10 = __ldg(w + 10);
    float2 w11 = __ldg(w + 11);
    float  s24 = __ldg(labels + a + 24);
    float  s25 = off ? __ldg(labels + a + 25) : 0.0f;   // a+25 = lb+24, in-bounds
    float tb0 = off ? w11.x : w10.y;
    float tb1 = off ? w11.y : w11.x;
    float tb2 = off ? s24   : w11.y;
    float tb3 = off ? s25   : s24;

    // transformed: o = [x/S, y/S, w^2, h^2]; t = [x/S, y/S, w, h]
    float o0x = b01.x * (1.0f / 7.0f), o0y = b01.y * (1.0f / 7.0f);
    float o0w = b23.x * b23.x,         o0h = b23.y * b23.y;
    float o1x = b45.x * (1.0f / 7.0f), o1y = b45.y * (1.0f / 7.0f);
    float o1w = b67.x * b67.x,         o1h = b67.y * b67.y;
    float tx = tb0 * (1.0f / 7.0f), ty = tb1 * (1.0f / 7.0f);
    float tw = tb2, th = tb3;

    float iou0, iou1, r0, r1;
    {
        float left   = fmaxf(tx - 0.5f * tw, o0x - 0.5f * o0w);
        float right  = fminf(tx + 0.5f * tw, o0x + 0.5f * o0w);
        float top    = fmaxf(ty - 0.5f * th, o0y - 0.5f * o0h);
        float bottom = fminf(ty + 0.5f * th, o0y + 0.5f * o0h);
        float wd = right - left, h = bottom - top;
        bool invalid = (wd < 0.0f) || (h < 0.0f);
        float inter = invalid ? 0.0f : wd * h;
        float uni = tw * th + o0w * o0h - inter;
        iou0 = invalid ? 0.0f : inter / fmaxf(uni, 1e-12f);
        float d0 = tx - o0x, d1 = ty - o0y, d2 = tw - o0w, d3 = th - o0h;
        r0 = d0 * d0 + d1 * d1 + d2 * d2 + d3 * d3;
    }
    {
        float left   = fmaxf(tx - 0.5f * tw, o1x - 0.5f * o1w);
        float right  = fminf(tx + 0.5f * tw, o1x + 0.5f * o1w);
        float top    = fmaxf(ty - 0.5f * th, o1y - 0.5f * o1h);
        float bottom = fminf(ty + 0.5f * th, o1y + 0.5f * o1h);
        float wd = right - left, h = bottom - top;
        bool invalid = (wd < 0.0f) || (h < 0.0f);
        float inter = invalid ? 0.0f : wd * h;
        float uni = tw * th + o1w * o1h - inter;
        iou1 = invalid ? 0.0f : inter / fmaxf(uni, 1e-12f);
        float d0 = tx - o1x, d1 = ty - o1y, d2 = tw - o1w, d3 = th - o1h;
        r1 = d0 * d0 + d1 * d1 + d2 * d2 + d3 * d3;
    }

    // argmax/argmin first-index tie semantics
    float miou = fmaxf(iou0, iou1);
    int best = (miou > 0.0f) ? ((iou1 > iou0) ? 1 : 0)
                             : ((r1 < r0) ? 1 : 0);

    float best_iou  = best ? iou1 : iou0;
    float conf_best = best ? pc.y : pc.x;
    float dcb = best_iou - conf_best;
    // correction vs unconditional NOOBJ*(cx^2+cy^2) base from phase 1
    float conf_corr = OBJ_W * dcb * dcb - NOOBJ_W * conf_best * conf_best;

    float pbx = best ? b45.x : b01.x;
    float pby = best ? b45.y : b01.y;
    float pbw = best ? b67.x : b23.x;
    float pbh = best ? b67.y : b23.y;
    float st2 = sqrtf(tb2), st3 = sqrtf(tb3);
    float e0 = tb0 - pbx, e1 = tb1 - pby;
    float e2 = st2 - pbw, e3 = st3 - pbh;
    float coord = COORD_W * (e0 * e0 + e1 * e1 + e2 * e2 + e3 * e3);

    return conf_corr + cls + coord;
}

__global__ void __launch_bounds__(THREADS) yolo_loss_kernel(
    const float* __restrict__ preds,
    const float* __restrict__ labels,
    int total_cells,
    float* __restrict__ out)
{
    __shared__ double s_red[NWARPS];
    __shared__ bool   s_last;

    const int tid  = threadIdx.x;
    const int lane = tid & 31;
    const int wid  = tid >> 5;
    const int base = blockIdx.x * CPB;
    const int wbase = wid * 32;

    // ===== phase 1: flags + pconf, front-batched (MLP = 8) ==================
    // flag loaded via the aligned f2 covering it — same line the obj-path
    // label window re-reads first (L1 temporal locality).
    float  flag[CPT];
    float2 pc[CPT];
    bool   valid[CPT];

    #pragma unroll
    for (int k = 0; k < CPT; k++) {
        int cell = base + k * THREADS + tid;
        valid[k] = cell < total_cells;
        int c = valid[k] ? cell : 0;
        int i = c / L_CELLS, l = c - (c / L_CELLS) * L_CELLS;
        unsigned lb = (unsigned)i * ROW_L + 25u * l;
        float2 fw = __ldg(reinterpret_cast<const float2*>(labels + (lb & ~1u)));
        flag[k] = (lb & 1u) ? fw.y : fw.x;
        pc[k]   = __ldg(reinterpret_cast<const float2*>(
                        preds + (size_t)i * ROW_P + 980 + 2 * l));
    }

    float vbase = 0.0f;
    unsigned bal[CPT];
    int T = 0;
    #pragma unroll
    for (int k = 0; k < CPT; k++) {
        if (valid[k])
            vbase += NOOBJ_W * (pc[k].x * pc[k].x + pc[k].y * pc[k].y);
        bal[k] = __ballot_sync(0xffffffffu, valid[k] && (flag[k] != 0.0f));
        T += __popc(bal[k]);
    }

    // ===== phase 2: per-warp obj processing (no barriers, no smem) ==========
    double vd = (double)vbase;
    for (int t = lane; t < T; t += 32) {
        int j = t;
        int cellLocal = 0;
        #pragma unroll
        for (int k = 0; k < CPT; k++) {
            int c = __popc(bal[k]);
            if (j >= 0 && j < c) {
                int pos = __fns(bal[k], 0, j + 1);
                cellLocal = k * THREADS + wbase + pos;
            }
            j -= c;
        }
        vd += (double)obj_cell_loss(preds, labels, base + cellLocal);
    }

    // ===== block reduction ===================================================
    #pragma unroll
    for (int off = 16; off > 0; off >>= 1)
        vd += __shfl_down_sync(0xffffffffu, vd, off);
    if (lane == 0) s_red[wid] = vd;
    __syncthreads();

    if (wid == 0) {
        double x = (lane < NWARPS) ? s_red[lane] : 0.0;
        #pragma unroll
        for (int off = 4; off > 0; off >>= 1)
            x += __shfl_down_sync(0xffffffffu, x, off);
        if (lane == 0) g_partials[blockIdx.x] = x;
    }
    __syncthreads();

    // ===== fused finalize: last block reduces all partials ===================
    if (tid == 0) {
        __threadfence();
        unsigned old = atomicInc(&g_counter, gridDim.x - 1);
        s_last = (old == gridDim.x - 1);
    }
    __syncthreads();

    if (s_last) {
        __threadfence();
        double s = 0.0;
        for (int i = tid; i < gridDim.x; i += THREADS)
            s += g_partials[i];
        #pragma unroll
        for (int off = 16; off > 0; off >>= 1)
            s += __shfl_down_sync(0xffffffffu, s, off);
        if (lane == 0) s_red[wid] = s;
        __syncthreads();
        if (wid == 0) {
            double x = (lane < NWARPS) ? s_red[lane] : 0.0;
            #pragma unroll
            for (int off = 4; off > 0; off >>= 1)
                x += __shfl_down_sync(0xffffffffu, x, off);
            if (lane == 0) out[0] = (float)x;
        }
    }
}

extern "C" void kernel_launch(void* const* d_in, const int* in_sizes, int n_in,
                              void* d_out, int out_size)
{
    const float* preds  = (const float*)d_in[0];
    const float* labels = (const float*)d_in[1];
    int n = in_sizes[0] / ROW_P;
    int total_cells = n * L_CELLS;

    int blocks = (total_cells + CPB - 1) / CPB;   // n=16384 -> 784 blocks
    if (blocks > MAX_BLOCKS) blocks = MAX_BLOCKS;

    // Maximize L1 carveout (we use ~65 B of smem): flag atoms and label
    // windows are re-read block-locally; bigger L1 keeps them resident.
    static bool carveout_set = false;
    if (!carveout_set) {
        cudaFuncSetAttribute(yolo_loss_kernel,
                             cudaFuncAttributePreferredSharedMemoryCarveout, 0);
        carveout_set = true;
    }

    yolo_loss_kernel<<<blocks, THREADS>>>(preds, labels, total_cells,
                                          (float*)d_out);
}

// round 16
// speedup vs baseline: 1.0117x; 1.0117x over previous
#include <cuda_runtime.h>

// YOLO-style detection loss — R14 (best: 21.0us) + L1-carveout only.
// preds:  (n, 1470) f32  [pcls 980 | pconf 98 | pbox 392]
// labels: (n, 1225) f32  per cell (25 floats): [flag | 20 cls | 4 box]

#define L_CELLS 49
#define ROW_P 1470
#define ROW_L 1225
#define NOOBJ_W 0.5f
#define OBJ_W 0.5f
#define CLS_W 0.5f
#define COORD_W 2.5f

#define THREADS 256
#define CPT 4
#define CPB (THREADS * CPT)
#define NWARPS (THREADS / 32)
#define MAX_BLOCKS 8192

__device__ double   g_partials[MAX_BLOCKS];
__device__ unsigned g_counter = 0;    // self-wrapping; replay-safe

__device__ __forceinline__ float obj_cell_loss(
    const float* __restrict__ preds,
    const float* __restrict__ labels,
    int cell)
{
    int i = cell / L_CELLS;
    int l = cell - i * L_CELLS;
    const float* p = preds + (size_t)i * ROW_P;

    // ===== label window: win[k] = labels[a+k], a = lb & ~1, off = lb & 1 ====
    // record element j == win[j + off]; win[2m]=w[m].x, win[2m+1]=w[m].y
    unsigned lb  = (unsigned)i * ROW_L + 25u * l;
    unsigned a   = lb & ~1u;
    bool     off = (lb & 1u) != 0u;
    const float2* w = reinterpret_cast<const float2*>(labels + a);

    // ===== pcls window: pv[c] = preds[g4 + c + off2] ========================
    // g = i*1470 + 20l, g mod 4 in {0,2}; window g4..g4+23 stays in-row.
    unsigned g    = (unsigned)i * ROW_P + 20u * l;
    unsigned g4   = g & ~3u;
    bool     off2 = (g & 3u) != 0u;     // 0 or 2
    const float4* q = reinterpret_cast<const float4*>(preds + g4);

    // ---- issue scattered single-use loads up front (evict-first) ----
    float2 pc = __ldcs(reinterpret_cast<const float2*>(p + 980 + l * 2));
    const float* pb = p + 1078 + l * 8;
    float2 b01 = __ldcs(reinterpret_cast<const float2*>(pb + 0));
    float2 b23 = __ldcs(reinterpret_cast<const float2*>(pb + 2));
    float2 b45 = __ldcs(reinterpret_cast<const float2*>(pb + 4));
    float2 b67 = __ldcs(reinterpret_cast<const float2*>(pb + 6));

    // ===== class loss: rolling label window vs f4 pcls window ==============
    float cls = 0.0f;
    {
        float2 wc = __ldg(w + 0);            // w[c/2] for c=0
        #pragma unroll
        for (int c = 0; c < 20; c += 2) {
            float2 wn = __ldg(w + (c / 2 + 1));
            float la1 = off ? wn.x : wc.y;
            float la2 = off ? wn.y : wn.x;

            float pv1, pv2;
            if ((c & 3) == 0) {
                float4 v = __ldcs(q + c / 4);
                pv1 = off2 ? v.z : v.x;
                pv2 = off2 ? v.w : v.y;
            } else {  // c % 4 == 2
                float4 vlo = __ldcs(q + c / 4);
                float4 vhi = __ldcs(q + (c / 4 + 1));
                pv1 = off2 ? vhi.x : vlo.z;
                pv2 = off2 ? vhi.y : vlo.w;
            }
            float d0 = la1 - pv1;
            float d1 = la2 - pv2;
            cls += d0 * d0 + d1 * d1;
            wc = wn;
        }
    }
    cls *= CLS_W;

    // ===== target box: la(21..24) ===========================================
    float2 w10 = __ldg(w + 10);
    float2 w11 = __ldg(w + 11);
    float  s24 = __ldg(labels + a + 24);
    float  s25 = off ? __ldg(labels + a + 25) : 0.0f;   // a+25 = lb+24, in-bounds
    float tb0 = off ? w11.x : w10.y;
    float tb1 = off ? w11.y : w11.x;
    float tb2 = off ? s24   : w11.y;
    float tb3 = off ? s25   : s24;

    // transformed: o = [x/S, y/S, w^2, h^2]; t = [x/S, y/S, w, h]
    float o0x = b01.x * (1.0f / 7.0f), o0y = b01.y * (1.0f / 7.0f);
    float o0w = b23.x * b23.x,         o0h = b23.y * b23.y;
    float o1x = b45.x * (1.0f / 7.0f), o1y = b45.y * (1.0f / 7.0f);
    float o1w = b67.x * b67.x,         o1h = b67.y * b67.y;
    float tx = tb0 * (1.0f / 7.0f), ty = tb1 * (1.0f / 7.0f);
    float tw = tb2, th = tb3;

    float iou0, iou1, r0, r1;
    {
        float left   = fmaxf(tx - 0.5f * tw, o0x - 0.5f * o0w);
        float right  = fminf(tx + 0.5f * tw, o0x + 0.5f * o0w);
        float top    = fmaxf(ty - 0.5f * th, o0y - 0.5f * o0h);
        float bottom = fminf(ty + 0.5f * th, o0y + 0.5f * o0h);
        float wd = right - left, h = bottom - top;
        bool invalid = (wd < 0.0f) || (h < 0.0f);
        float inter = invalid ? 0.0f : wd * h;
        float uni = tw * th + o0w * o0h - inter;
        iou0 = invalid ? 0.0f : inter / fmaxf(uni, 1e-12f);
        float d0 = tx - o0x, d1 = ty - o0y, d2 = tw - o0w, d3 = th - o0h;
        r0 = d0 * d0 + d1 * d1 + d2 * d2 + d3 * d3;
    }
    {
        float left   = fmaxf(tx - 0.5f * tw, o1x - 0.5f * o1w);
        float right  = fminf(tx + 0.5f * tw, o1x + 0.5f * o1w);
        float top    = fmaxf(ty - 0.5f * th, o1y - 0.5f * o1h);
        float bottom = fminf(ty + 0.5f * th, o1y + 0.5f * o1h);
        float wd = right - left, h = bottom - top;
        bool invalid = (wd < 0.0f) || (h < 0.0f);
        float inter = invalid ? 0.0f : wd * h;
        float uni = tw * th + o1w * o1h - inter;
        iou1 = invalid ? 0.0f : inter / fmaxf(uni, 1e-12f);
        float d0 = tx - o1x, d1 = ty - o1y, d2 = tw - o1w, d3 = th - o1h;
        r1 = d0 * d0 + d1 * d1 + d2 * d2 + d3 * d3;
    }

    // argmax/argmin first-index tie semantics
    float miou = fmaxf(iou0, iou1);
    int best = (miou > 0.0f) ? ((iou1 > iou0) ? 1 : 0)
                             : ((r1 < r0) ? 1 : 0);

    float best_iou  = best ? iou1 : iou0;
    float conf_best = best ? pc.y : pc.x;
    float dcb = best_iou - conf_best;
    // correction vs unconditional NOOBJ*(cx^2+cy^2) base from phase 1
    float conf_corr = OBJ_W * dcb * dcb - NOOBJ_W * conf_best * conf_best;

    float pbx = best ? b45.x : b01.x;
    float pby = best ? b45.y : b01.y;
    float pbw = best ? b67.x : b23.x;
    float pbh = best ? b67.y : b23.y;
    float st2 = sqrtf(tb2), st3 = sqrtf(tb3);
    float e0 = tb0 - pbx, e1 = tb1 - pby;
    float e2 = st2 - pbw, e3 = st3 - pbh;
    float coord = COORD_W * (e0 * e0 + e1 * e1 + e2 * e2 + e3 * e3);

    return conf_corr + cls + coord;
}

__global__ void __launch_bounds__(THREADS) yolo_loss_kernel(
    const float* __restrict__ preds,
    const float* __restrict__ labels,
    int total_cells,
    float* __restrict__ out)
{
    __shared__ double s_red[NWARPS];
    __shared__ bool   s_last;

    const int tid  = threadIdx.x;
    const int lane = tid & 31;
    const int wid  = tid >> 5;
    const int base = blockIdx.x * CPB;
    const int wbase = wid * 32;

    // ===== phase 1: flags + pconf, front-batched (MLP = 8) ==================
    float  flag[CPT];
    float2 pc[CPT];
    bool   valid[CPT];

    #pragma unroll
    for (int k = 0; k < CPT; k++) {
        int cell = base + k * THREADS + tid;
        valid[k] = cell < total_cells;
        int c = valid[k] ? cell : 0;
        int i = c / L_CELLS, l = c - (c / L_CELLS) * L_CELLS;
        flag[k] = __ldg(labels + (size_t)i * ROW_L + 25 * l);
        pc[k]   = __ldg(reinterpret_cast<const float2*>(
                        preds + (size_t)i * ROW_P + 980 + 2 * l));
    }

    float vbase = 0.0f;
    unsigned bal[CPT];
    int T = 0;
    #pragma unroll
    for (int k = 0; k < CPT; k++) {
        if (valid[k])
            vbase += NOOBJ_W * (pc[k].x * pc[k].x + pc[k].y * pc[k].y);
        bal[k] = __ballot_sync(0xffffffffu, valid[k] && (flag[k] != 0.0f));
        T += __popc(bal[k]);
    }

    // ===== phase 2: per-warp obj processing (no barriers, no smem) ==========
    double vd = (double)vbase;
    for (int t = lane; t < T; t += 32) {
        int j = t;
        int cellLocal = 0;
        #pragma unroll
        for (int k = 0; k < CPT; k++) {
            int c = __popc(bal[k]);
            if (j >= 0 && j < c) {
                int pos = __fns(bal[k], 0, j + 1);
                cellLocal = k * THREADS + wbase + pos;
            }
            j -= c;
        }
        vd += (double)obj_cell_loss(preds, labels, base + cellLocal);
    }

    // ===== block reduction ===================================================
    #pragma unroll
    for (int off = 16; off > 0; off >>= 1)
        vd += __shfl_down_sync(0xffffffffu, vd, off);
    if (lane == 0) s_red[wid] = vd;
    __syncthreads();

    if (wid == 0) {
        double x = (lane < NWARPS) ? s_red[lane] : 0.0;
        #pragma unroll
        for (int off = 4; off > 0; off >>= 1)
            x += __shfl_down_sync(0xffffffffu, x, off);
        if (lane == 0) g_partials[blockIdx.x] = x;
    }
    __syncthreads();

    // ===== fused finalize: last block reduces all partials ===================
    if (tid == 0) {
        __threadfence();
        unsigned old = atomicInc(&g_counter, gridDim.x - 1);
        s_last = (old == gridDim.x - 1);
    }
    __syncthreads();

    if (s_last) {
        __threadfence();
        double s = 0.0;
        for (int i = tid; i < gridDim.x; i += THREADS)
            s += g_partials[i];
        #pragma unroll
        for (int off = 16; off > 0; off >>= 1)
            s += __shfl_down_sync(0xffffffffu, s, off);
        if (lane == 0) s_red[wid] = s;
        __syncthreads();
        if (wid == 0) {
            double x = (lane < NWARPS) ? s_red[lane] : 0.0;
            #pragma unroll
            for (int off = 4; off > 0; off >>= 1)
                x += __shfl_down_sync(0xffffffffu, x, off);
            if (lane == 0) out[0] = (float)x;
        }
    }
}

extern "C" void kernel_launch(void* const* d_in, const int* in_sizes, int n_in,
                              void* d_out, int out_size)
{
    const float* preds  = (const float*)d_in[0];
    const float* labels = (const float*)d_in[1];
    int n = in_sizes[0] / ROW_P;
    int total_cells = n * L_CELLS;

    int blocks = (total_cells + CPB - 1) / CPB;   // n=16384 -> 784 blocks
    if (blocks > MAX_BLOCKS) blocks = MAX_BLOCKS;

    // Maximize L1 carveout (we use ~65 B of smem): label atoms fetched in
    // phase 1 get re-read by the obj-path windows; bigger L1 keeps them hot.
    static bool carveout_set = false;
    if (!carveout_set) {
        cudaFuncSetAttribute(yolo_loss_kernel,
                             cudaFuncAttributePreferredSharedMemoryCarveout, 0);
        carveout_set = true;
    }

    yolo_loss_kernel<<<blocks, THREADS>>>(preds, labels, total_cells,
                                          (float*)d_out);
}

// round 17
// speedup vs baseline: 1.0549x; 1.0427x over previous
#include <cuda_runtime.h>

// YOLO-style detection loss — FINAL (R14 config, best measured 21.0us).
// preds:  (n, 1470) f32  [pcls 980 | pconf 98 | pbox 392]
// labels: (n, 1225) f32  per cell (25 floats): [flag | 20 cls | 4 box]
//
// Structure: per-warp ballot compaction (no barriers in mainline),
// unconditional NOOBJ base + obj-path correction, wide windowed loads
// consumed in-place, __ldcs on single-use streams, fused last-block finalize.

#define L_CELLS 49
#define ROW_P 1470
#define ROW_L 1225
#define NOOBJ_W 0.5f
#define OBJ_W 0.5f
#define CLS_W 0.5f
#define COORD_W 2.5f

#define THREADS 256
#define CPT 4
#define CPB (THREADS * CPT)
#define NWARPS (THREADS / 32)
#define MAX_BLOCKS 8192

__device__ double   g_partials[MAX_BLOCKS];
__device__ unsigned g_counter = 0;    // self-wrapping; replay-safe

__device__ __forceinline__ float obj_cell_loss(
    const float* __restrict__ preds,
    const float* __restrict__ labels,
    int cell)
{
    int i = cell / L_CELLS;
    int l = cell - i * L_CELLS;
    const float* p = preds + (size_t)i * ROW_P;

    // ===== label window: win[k] = labels[a+k], a = lb & ~1, off = lb & 1 ====
    // record element j == win[j + off]; win[2m]=w[m].x, win[2m+1]=w[m].y
    unsigned lb  = (unsigned)i * ROW_L + 25u * l;
    unsigned a   = lb & ~1u;
    bool     off = (lb & 1u) != 0u;
    const float2* w = reinterpret_cast<const float2*>(labels + a);

    // ===== pcls window: pv[c] = preds[g4 + c + off2] ========================
    // g = i*1470 + 20l, g mod 4 in {0,2}; window g4..g4+23 stays in-row.
    unsigned g    = (unsigned)i * ROW_P + 20u * l;
    unsigned g4   = g & ~3u;
    bool     off2 = (g & 3u) != 0u;     // 0 or 2
    const float4* q = reinterpret_cast<const float4*>(preds + g4);

    // ---- issue scattered single-use loads up front (evict-first) ----
    float2 pc = __ldcs(reinterpret_cast<const float2*>(p + 980 + l * 2));
    const float* pb = p + 1078 + l * 8;
    float2 b01 = __ldcs(reinterpret_cast<const float2*>(pb + 0));
    float2 b23 = __ldcs(reinterpret_cast<const float2*>(pb + 2));
    float2 b45 = __ldcs(reinterpret_cast<const float2*>(pb + 4));
    float2 b67 = __ldcs(reinterpret_cast<const float2*>(pb + 6));

    // ===== class loss: rolling label window vs f4 pcls window ==============
    float cls = 0.0f;
    {
        float2 wc = __ldg(w + 0);            // w[c/2] for c=0
        #pragma unroll
        for (int c = 0; c < 20; c += 2) {
            float2 wn = __ldg(w + (c / 2 + 1));
            float la1 = off ? wn.x : wc.y;
            float la2 = off ? wn.y : wn.x;

            float pv1, pv2;
            if ((c & 3) == 0) {
                float4 v = __ldcs(q + c / 4);
                pv1 = off2 ? v.z : v.x;
                pv2 = off2 ? v.w : v.y;
            } else {  // c % 4 == 2
                float4 vlo = __ldcs(q + c / 4);
                float4 vhi = __ldcs(q + (c / 4 + 1));
                pv1 = off2 ? vhi.x : vlo.z;
                pv2 = off2 ? vhi.y : vlo.w;
            }
            float d0 = la1 - pv1;
            float d1 = la2 - pv2;
            cls += d0 * d0 + d1 * d1;
            wc = wn;
        }
    }
    cls *= CLS_W;

    // ===== target box: la(21..24) ===========================================
    float2 w10 = __ldg(w + 10);
    float2 w11 = __ldg(w + 11);
    float  s24 = __ldg(labels + a + 24);
    float  s25 = off ? __ldg(labels + a + 25) : 0.0f;   // a+25 = lb+24, in-bounds
    float tb0 = off ? w11.x : w10.y;
    float tb1 = off ? w11.y : w11.x;
    float tb2 = off ? s24   : w11.y;
    float tb3 = off ? s25   : s24;

    // transformed: o = [x/S, y/S, w^2, h^2]; t = [x/S, y/S, w, h]
    float o0x = b01.x * (1.0f / 7.0f), o0y = b01.y * (1.0f / 7.0f);
    float o0w = b23.x * b23.x,         o0h = b23.y * b23.y;
    float o1x = b45.x * (1.0f / 7.0f), o1y = b45.y * (1.0f / 7.0f);
    float o1w = b67.x * b67.x,         o1h = b67.y * b67.y;
    float tx = tb0 * (1.0f / 7.0f), ty = tb1 * (1.0f / 7.0f);
    float tw = tb2, th = tb3;

    float iou0, iou1, r0, r1;
    {
        float left   = fmaxf(tx - 0.5f * tw, o0x - 0.5f * o0w);
        float right  = fminf(tx + 0.5f * tw, o0x + 0.5f * o0w);
        float top    = fmaxf(ty - 0.5f * th, o0y - 0.5f * o0h);
        float bottom = fminf(ty + 0.5f * th, o0y + 0.5f * o0h);
        float wd = right - left, h = bottom - top;
        bool invalid = (wd < 0.0f) || (h < 0.0f);
        float inter = invalid ? 0.0f : wd * h;
        float uni = tw * th + o0w * o0h - inter;
        iou0 = invalid ? 0.0f : inter / fmaxf(uni, 1e-12f);
        float d0 = tx - o0x, d1 = ty - o0y, d2 = tw - o0w, d3 = th - o0h;
        r0 = d0 * d0 + d1 * d1 + d2 * d2 + d3 * d3;
    }
    {
        float left   = fmaxf(tx - 0.5f * tw, o1x - 0.5f * o1w);
        float right  = fminf(tx + 0.5f * tw, o1x + 0.5f * o1w);
        float top    = fmaxf(ty - 0.5f * th, o1y - 0.5f * o1h);
        float bottom = fminf(ty + 0.5f * th, o1y + 0.5f * o1h);
        float wd = right - left, h = bottom - top;
        bool invalid = (wd < 0.0f) || (h < 0.0f);
        float inter = invalid ? 0.0f : wd * h;
        float uni = tw * th + o1w * o1h - inter;
        iou1 = invalid ? 0.0f : inter / fmaxf(uni, 1e-12f);
        float d0 = tx - o1x, d1 = ty - o1y, d2 = tw - o1w, d3 = th - o1h;
        r1 = d0 * d0 + d1 * d1 + d2 * d2 + d3 * d3;
    }

    // argmax/argmin first-index tie semantics
    float miou = fmaxf(iou0, iou1);
    int best = (miou > 0.0f) ? ((iou1 > iou0) ? 1 : 0)
                             : ((r1 < r0) ? 1 : 0);

    float best_iou  = best ? iou1 : iou0;
    float conf_best = best ? pc.y : pc.x;
    float dcb = best_iou - conf_best;
    // correction vs unconditional NOOBJ*(cx^2+cy^2) base from phase 1
    float conf_corr = OBJ_W * dcb * dcb - NOOBJ_W * conf_best * conf_best;

    float pbx = best ? b45.x : b01.x;
    float pby = best ? b45.y : b01.y;
    float pbw = best ? b67.x : b23.x;
    float pbh = best ? b67.y : b23.y;
    float st2 = sqrtf(tb2), st3 = sqrtf(tb3);
    float e0 = tb0 - pbx, e1 = tb1 - pby;
    float e2 = st2 - pbw, e3 = st3 - pbh;
    float coord = COORD_W * (e0 * e0 + e1 * e1 + e2 * e2 + e3 * e3);

    return conf_corr + cls + coord;
}

__global__ void __launch_bounds__(THREADS) yolo_loss_kernel(
    const float* __restrict__ preds,
    const float* __restrict__ labels,
    int total_cells,
    float* __restrict__ out)
{
    __shared__ double s_red[NWARPS];
    __shared__ bool   s_last;

    const int tid  = threadIdx.x;
    const int lane = tid & 31;
    const int wid  = tid >> 5;
    const int base = blockIdx.x * CPB;
    const int wbase = wid * 32;

    // ===== phase 1: flags + pconf, front-batched (MLP = 8) ==================
    float  flag[CPT];
    float2 pc[CPT];
    bool   valid[CPT];

    #pragma unroll
    for (int k = 0; k < CPT; k++) {
        int cell = base + k * THREADS + tid;
        valid[k] = cell < total_cells;
        int c = valid[k] ? cell : 0;
        int i = c / L_CELLS, l = c - (c / L_CELLS) * L_CELLS;
        flag[k] = __ldg(labels + (size_t)i * ROW_L + 25 * l);
        pc[k]   = __ldg(reinterpret_cast<const float2*>(
                        preds + (size_t)i * ROW_P + 980 + 2 * l));
    }

    float vbase = 0.0f;
    unsigned bal[CPT];
    int T = 0;
    #pragma unroll
    for (int k = 0; k < CPT; k++) {
        if (valid[k])
            vbase += NOOBJ_W * (pc[k].x * pc[k].x + pc[k].y * pc[k].y);
        bal[k] = __ballot_sync(0xffffffffu, valid[k] && (flag[k] != 0.0f));
        T += __popc(bal[k]);
    }

    // ===== phase 2: per-warp obj processing (no barriers, no smem) ==========
    double vd = (double)vbase;
    for (int t = lane; t < T; t += 32) {
        int j = t;
        int cellLocal = 0;
        #pragma unroll
        for (int k = 0; k < CPT; k++) {
            int c = __popc(bal[k]);
            if (j >= 0 && j < c) {
                int pos = __fns(bal[k], 0, j + 1);
                cellLocal = k * THREADS + wbase + pos;
            }
            j -= c;
        }
        vd += (double)obj_cell_loss(preds, labels, base + cellLocal);
    }

    // ===== block reduction ===================================================
    #pragma unroll
    for (int off = 16; off > 0; off >>= 1)
        vd += __shfl_down_sync(0xffffffffu, vd, off);
    if (lane == 0) s_red[wid] = vd;
    __syncthreads();

    if (wid == 0) {
        double x = (lane < NWARPS) ? s_red[lane] : 0.0;
        #pragma unroll
        for (int off = 4; off > 0; off >>= 1)
            x += __shfl_down_sync(0xffffffffu, x, off);
        if (lane == 0) g_partials[blockIdx.x] = x;
    }
    __syncthreads();

    // ===== fused finalize: last block reduces all partials ===================
    if (tid == 0) {
        __threadfence();
        unsigned old = atomicInc(&g_counter, gridDim.x - 1);
        s_last = (old == gridDim.x - 1);
    }
    __syncthreads();

    if (s_last) {
        __threadfence();
        double s = 0.0;
        for (int i = tid; i < gridDim.x; i += THREADS)
            s += g_partials[i];
        #pragma unroll
        for (int off = 16; off > 0; off >>= 1)
            s += __shfl_down_sync(0xffffffffu, s, off);
        if (lane == 0) s_red[wid] = s;
        __syncthreads();
        if (wid == 0) {
            double x = (lane < NWARPS) ? s_red[lane] : 0.0;
            #pragma unroll
            for (int off = 4; off > 0; off >>= 1)
                x += __shfl_down_sync(0xffffffffu, x, off);
            if (lane == 0) out[0] = (float)x;
        }
    }
}

extern "C" void kernel_launch(void* const* d_in, const int* in_sizes, int n_in,
                              void* d_out, int out_size)
{
    const float* preds  = (const float*)d_in[0];
    const float* labels = (const float*)d_in[1];
    int n = in_sizes[0] / ROW_P;
    int total_cells = n * L_CELLS;

    int blocks = (total_cells + CPB - 1) / CPB;   // n=16384 -> 784 blocks
    if (blocks > MAX_BLOCKS) blocks = MAX_BLOCKS;

    yolo_loss_kernel<<<blocks, THREADS>>>(preds, labels, total_cells,
                                          (float*)d_out);
}